// round 12
// baseline (speedup 1.0000x reference)
#include <cuda_runtime.h>
#include <cstdint>

// IndRNN recurrent-only: h_t = relu(x_t + w * h_{t-1})
// x: [T=2048, B=64, H=512] f32. 512MB traffic floor.
// R12: R11 pipeline, but consumers rebalanced across all 4 SMSPs.
//   consumers: warps 0-3 (tid 0..127), one float2-column each: LDS.64+FMA+STG.64
//   producers: warps 4-5 (tid 128..191), one float4-column each: cp.async.cg 16B
// Producer byte pattern identical to R11 (float4 covers two float2 cols).
// mbarrier ring: full (64 producer arrivals), empty (128 consumer arrivals).

#define T_LEN 2048
#define B_DIM 64
#define H_DIM 512
#define NCH (B_DIM * H_DIM)       // 32768 chains
#define C2_PER_CTA 128            // float2 columns per CTA
#define C4_PER_CTA 64             // float4 columns per CTA (producer view)
#define GRID 128
#define TPB 192
#define U 32                      // timesteps per stage
#define NSTAGE 6
#define NTILES (T_LEN / U)        // 64
#define STAGE_BYTES (U * C4_PER_CTA * 16)             // 32768
#define DATA_OFF 1024
#define SMEM_BYTES (DATA_OFF + NSTAGE * STAGE_BYTES)  // 197632

__device__ __forceinline__ void cp_async16(uint32_t saddr, const void* gptr) {
    asm volatile("cp.async.cg.shared.global [%0], [%1], 16;"
                 :: "r"(saddr), "l"(gptr));
}

__device__ __forceinline__ void mbar_init(uint32_t addr, uint32_t cnt) {
    asm volatile("mbarrier.init.shared.b64 [%0], %1;" :: "r"(addr), "r"(cnt) : "memory");
}

__device__ __forceinline__ void mbar_arrive(uint32_t addr) {
    asm volatile("mbarrier.arrive.shared.b64 _, [%0];" :: "r"(addr) : "memory");
}

__device__ __forceinline__ void cp_async_mbar_arrive(uint32_t addr) {
    asm volatile("cp.async.mbarrier.arrive.noinc.shared.b64 [%0];" :: "r"(addr) : "memory");
}

__device__ __forceinline__ void mbar_wait(uint32_t addr, uint32_t p) {
    uint32_t done;
    asm volatile(
        "{\n\t.reg .pred q;\n\t"
        "mbarrier.try_wait.parity.acquire.cta.shared::cta.b64 q, [%1], %2;\n\t"
        "selp.b32 %0, 1, 0, q;\n\t}"
        : "=r"(done) : "r"(addr), "r"(p) : "memory");
    if (!done) {
        asm volatile(
            "{\n\t.reg .pred q;\n\t"
            "WL_%=:\n\t"
            "mbarrier.try_wait.parity.acquire.cta.shared::cta.b64 q, [%0], %1, 0x989680;\n\t"
            "@q bra.uni WD_%=;\n\t"
            "bra.uni WL_%=;\n\t"
            "WD_%=:\n\t}"
            :: "r"(addr), "r"(p) : "memory");
    }
}

__global__ __launch_bounds__(TPB, 1)
void indrnn_scan_kernel(const float* __restrict__ x,
                        const float* __restrict__ w,
                        float* __restrict__ out) {
    extern __shared__ char smem[];
    const uint32_t sbase = (uint32_t)__cvta_generic_to_shared(smem);
    const uint32_t bar = sbase;              // full[s]@s*16, empty[s]@s*16+8
    const uint32_t data = sbase + DATA_OFF;

    const int tid = threadIdx.x;

    if (tid == 0) {
        #pragma unroll
        for (int s = 0; s < NSTAGE; ++s) {
            mbar_init(bar + s * 16,     C4_PER_CTA);   // full: 64 producer arrivals
            mbar_init(bar + s * 16 + 8, C2_PER_CTA);   // empty: 128 consumer arrivals
        }
    }
    __syncthreads();

    if (tid >= 128) {
        // ---------------- Producer (warps 4-5): float4 cp.async stream ----------
        const int p = tid - 128;                       // 0..63
        const int cid4 = blockIdx.x * C4_PER_CTA + p;  // global float4 column
        const int stride4 = NCH / 4;                   // 8192
        const float4* xp = reinterpret_cast<const float4*>(x) + cid4;
        int stage = 0, phase = 1;                      // first empty-wait passes
        for (int tile = 0; tile < NTILES; ++tile) {
            mbar_wait(bar + stage * 16 + 8, phase);    // wait empty
            const float4* g = xp + (size_t)tile * U * stride4;
            const uint32_t sb = data + (uint32_t)stage * STAGE_BYTES + (uint32_t)p * 16u;
            #pragma unroll
            for (int u = 0; u < U; ++u)
                cp_async16(sb + (uint32_t)(u * C4_PER_CTA) * 16u,
                           g + (size_t)u * stride4);
            cp_async_mbar_arrive(bar + stage * 16);    // async arrive on full
            if (++stage == NSTAGE) { stage = 0; phase ^= 1; }
        }
    } else {
        // ---------------- Consumer (warps 0-3): float2 chain per thread ---------
        const int col = tid;                           // 0..127 float2 column
        const int cid2 = blockIdx.x * C2_PER_CTA + col;
        const int stride2 = NCH / 2;                   // 16384
        const float2 wv = *reinterpret_cast<const float2*>(
            w + ((cid2 & (H_DIM / 2 - 1)) << 1));
        float2* op = reinterpret_cast<float2*>(out) + cid2;
        float2 h = make_float2(0.f, 0.f);

        int stage = 0, phase = 0;
        for (int tile = 0; tile < NTILES; ++tile) {
            mbar_wait(bar + stage * 16, phase);        // wait full
            const float2* sp = reinterpret_cast<const float2*>(
                smem + DATA_OFF + (size_t)stage * STAGE_BYTES) + col;
            float2* ob = op + (size_t)tile * U * stride2;
            #pragma unroll
            for (int u = 0; u < U; ++u) {
                float2 v = sp[(size_t)u * C2_PER_CTA];
                h.x = fmaxf(fmaf(wv.x, h.x, v.x), 0.0f);
                h.y = fmaxf(fmaf(wv.y, h.y, v.y), 0.0f);
                __stcs(ob + (size_t)u * stride2, h);
            }
            mbar_arrive(bar + stage * 16 + 8);         // release stage
            if (++stage == NSTAGE) { stage = 0; phase ^= 1; }
        }
    }
}

extern "C" void kernel_launch(void* const* d_in, const int* in_sizes, int n_in,
                              void* d_out, int out_size) {
    const float* x = (const float*)d_in[0];
    const float* w = (const float*)d_in[1];
    float* out = (float*)d_out;

    cudaFuncSetAttribute(indrnn_scan_kernel,
                         cudaFuncAttributeMaxDynamicSharedMemorySize, SMEM_BYTES);

    indrnn_scan_kernel<<<GRID, TPB, SMEM_BYTES>>>(x, w, out);
}